// round 3
// baseline (speedup 1.0000x reference)
#include <cuda_runtime.h>
#include <math.h>

#define NROI 1024
#define NCLS 21
#define APP  1024
#define DF   128
#define NH   16
#define DK   64

// ---------------- scratch (device globals; no allocation allowed) -------------
__device__ float g_S[NH * NROI * NROI];   // 64 MB: scores k.q/8  [h][m][n]
__device__ float g_K[NH * NROI * DK];     // [h][n][kk]
__device__ float g_Q[NH * NROI * DK];     // [h][n][kk]
__device__ float g_emb[NROI * DF];        // emb_feat (sorted order)
__device__ float g_vl[NH * NROI];         // vl[h][n] = v[h,n,:].lw_h
__device__ float g_wvl[NH * DF];          // wv_w[h] @ lw_h
__device__ float g_bvl[NH];               // wv_b[h] . lw_h
__device__ float g_prob[NROI], g_sprob[NROI], g_attn[NROI], g_sflw[NROI];
__device__ float g_bbox[NROI * 4], g_sbbox[NROI * 4], g_sgeo[NROI * 4];
__device__ int   g_label[NROI], g_slabel[NROI], g_order[NROI];

// ---------------- K1: per-ROI softmax / argmax / bbox decode ------------------
__global__ void k_perroi(const float* __restrict__ roi,
                         const float* __restrict__ cls_loc,
                         const float* __restrict__ score,
                         const int*   __restrict__ size) {
    int i = blockIdx.x * blockDim.x + threadIdx.x;
    if (i >= NROI) return;
    const float* s = score + i * NCLS;
    float mx = -1e30f; int am = 0;
    for (int c = 0; c < NCLS; c++) { float v = s[c]; if (v > mx) { mx = v; am = c; } }
    float sum = 0.f;
    for (int c = 0; c < NCLS; c++) sum += expf(s[c] - mx);
    g_prob[i] = 1.0f / sum;       // max of softmax
    g_label[i] = am;
    float y0 = roi[i*4+0], x0 = roi[i*4+1], y1 = roi[i*4+2], x1 = roi[i*4+3];
    float h = y1 - y0, w = x1 - x0;
    float cy = y0 + 0.5f * h, cx = x0 + 0.5f * w;
    const float* l = cls_loc + i * (NCLS*4) + am * 4;
    float dy = l[0]*0.1f, dx = l[1]*0.1f, dh = l[2]*0.2f, dw = l[3]*0.2f;
    float ncy = dy*h + cy, ncx = dx*w + cx;
    float nh = expf(dh)*h, nw = expf(dw)*w;
    float b0 = ncy - 0.5f*nh, b1 = ncx - 0.5f*nw, b2 = ncy + 0.5f*nh, b3 = ncx + 0.5f*nw;
    // replicate original clamp quirk: even class -> clamp ALL coords to size[0],
    // odd class -> clamp ALL coords to size[1]
    float lim = ((am & 1) == 0) ? (float)size[0] : (float)size[1];
    b0 = fminf(fmaxf(b0, 0.f), lim);
    b1 = fminf(fmaxf(b1, 0.f), lim);
    b2 = fminf(fmaxf(b2, 0.f), lim);
    b3 = fminf(fmaxf(b3, 0.f), lim);
    g_bbox[i*4+0]=b0; g_bbox[i*4+1]=b1; g_bbox[i*4+2]=b2; g_bbox[i*4+3]=b3;
}

// ---------------- K2: stable descending rank + scatter ------------------------
__global__ void k_rank() {
    int i = blockIdx.x * blockDim.x + threadIdx.x;
    if (i >= NROI) return;
    float p = g_prob[i];
    int r = 0;
    for (int j = 0; j < NROI; j++) {
        float pj = g_prob[j];
        r += (pj > p) || (pj == p && j < i);   // stable descending
    }
    g_order[r]  = i;
    g_sprob[r]  = p;
    g_slabel[r] = g_label[i];
    float b0=g_bbox[i*4+0], b1=g_bbox[i*4+1], b2=g_bbox[i*4+2], b3=g_bbox[i*4+3];
    g_sbbox[r*4+0]=b0; g_sbbox[r*4+1]=b1; g_sbbox[r*4+2]=b2; g_sbbox[r*4+3]=b3;
    // positional-embedding geometry (note: column names follow the reference,
    // which treats col0 as x_min even though storage is y0,x0,y1,x1)
    float cx = (b0+b2)*0.5f, cy = (b1+b3)*0.5f;
    float w  = (b2-b0)+1.0f, h  = (b3-b1)+1.0f;
    g_sgeo[r*4+0]=cx; g_sgeo[r*4+1]=cy; g_sgeo[r*4+2]=w; g_sgeo[r*4+3]=h;
}

// ---------------- K3: emb_feat = sf@feat_w + feat_b + RE@rank_w + rank_b ------
__global__ __launch_bounds__(DF) void k_emb(const float* __restrict__ app,
                                            const float* __restrict__ rank_w,
                                            const float* __restrict__ rank_b,
                                            const float* __restrict__ feat_w,
                                            const float* __restrict__ feat_b,
                                            const float* __restrict__ lw) {
    __shared__ float arow[APP];
    __shared__ float rerow[APP];
    __shared__ float red[DF];
    int i = blockIdx.x;           // sorted position
    int t = threadIdx.x;          // 0..127
    int oi = g_order[i];
    const float LOGW = 6.90775528f / 512.0f;   // log(1000)/512
    for (int j = t; j < APP; j += DF) {
        arow[j] = app[oi * APP + j];
        int f = (j < 512) ? j : (j - 512);
        float arg = (float)i * expf(-(float)f * LOGW);
        rerow[j] = (j < 512) ? sinf(arg) : cosf(arg);
    }
    __syncthreads();
    float acc = feat_b[t] + rank_b[t];
    for (int j = 0; j < APP; j++) {
        acc += arow[j] * feat_w[j * DF + t] + rerow[j] * rank_w[j * DF + t];
    }
    g_emb[i * DF + t] = acc;
    // sflw[i] = sorted_features[i] . logit_w
    float pl = 0.f;
    for (int j = t; j < APP; j += DF) pl += arow[j] * lw[j];
    red[t] = pl; __syncthreads();
    for (int s = 64; s > 0; s >>= 1) { if (t < s) red[t] += red[t + s]; __syncthreads(); }
    if (t == 0) g_sflw[i] = red[0];
}

// ---------------- K4a: wvl[h][d] = sum_kk wv_w[h,d,kk]*lw[h*64+kk] ------------
__global__ void k_wvl(const float* __restrict__ wv_w,
                      const float* __restrict__ wv_b,
                      const float* __restrict__ lw) {
    int gt = blockIdx.x * blockDim.x + threadIdx.x;
    if (gt < NH * DF) {
        int h = gt >> 7, d = gt & 127;
        const float* W = wv_w + (h * DF + d) * DK;
        const float* L = lw + h * DK;
        float a = 0.f;
        for (int kk = 0; kk < DK; kk++) a += W[kk] * L[kk];
        g_wvl[gt] = a;
    }
    if (gt < NH) {
        const float* B = wv_b + gt * DK;
        const float* L = lw + gt * DK;
        float a = 0.f;
        for (int kk = 0; kk < DK; kk++) a += B[kk] * L[kk];
        g_bvl[gt] = a;
    }
}

// ---------------- K4b: k,q projections + vl -----------------------------------
__global__ __launch_bounds__(256) void k_kqv(const float* __restrict__ wk_w,
                                             const float* __restrict__ wk_b,
                                             const float* __restrict__ wq_w,
                                             const float* __restrict__ wq_b) {
    __shared__ float e[DF];
    int i = blockIdx.x, t = threadIdx.x;
    if (t < DF) e[t] = g_emb[i * DF + t];
    __syncthreads();
    for (int p = t; p < NH * DK; p += 256) {
        int h = p >> 6, kk = p & 63;
        float ak = wk_b[h * DK + kk];
        float aq = wq_b[h * DK + kk];
        const float* Wk = wk_w + h * DF * DK + kk;
        const float* Wq = wq_w + h * DF * DK + kk;
        for (int d = 0; d < DF; d++) {
            float ed = e[d];
            ak += ed * Wk[d * DK];
            aq += ed * Wq[d * DK];
        }
        g_K[(h * NROI + i) * DK + kk] = ak;
        g_Q[(h * NROI + i) * DK + kk] = aq;
    }
    if (t < NH) {
        float a = g_bvl[t];
        const float* W = g_wvl + t * DF;
        for (int d = 0; d < DF; d++) a += e[d] * W[d];
        g_vl[t * NROI + i] = a;
    }
}

// ---------------- K5: tiled score GEMM  S[h,m,n] = K[h,m,:].Q[h,n,:]/8 --------
__global__ __launch_bounds__(256) void k_score() {
    __shared__ float Ks[64][65];
    __shared__ float Qs[64][65];
    int h = blockIdx.z, mt = blockIdx.y, nt = blockIdx.x;
    int t = threadIdx.x;
    for (int idx = t; idx < 64 * 64; idx += 256) {
        int r = idx >> 6, c = idx & 63;
        Ks[r][c] = g_K[(h * NROI + mt * 64 + r) * DK + c];
        Qs[r][c] = g_Q[(h * NROI + nt * 64 + r) * DK + c];
    }
    __syncthreads();
    int ty = t >> 4, tx = t & 15;
    float acc[4][4] = {};
    for (int kk = 0; kk < 64; kk++) {
        float a[4], b[4];
        #pragma unroll
        for (int ii = 0; ii < 4; ii++) a[ii] = Ks[ty * 4 + ii][kk];
        #pragma unroll
        for (int jj = 0; jj < 4; jj++) b[jj] = Qs[tx * 4 + jj][kk];
        #pragma unroll
        for (int ii = 0; ii < 4; ii++)
            #pragma unroll
            for (int jj = 0; jj < 4; jj++)
                acc[ii][jj] += a[ii] * b[jj];
    }
    #pragma unroll
    for (int ii = 0; ii < 4; ii++) {
        int m = mt * 64 + ty * 4 + ii;
        #pragma unroll
        for (int jj = 0; jj < 4; jj++) {
            int n = nt * 64 + tx * 4 + jj;
            g_S[(h << 20) + (m << 10) + n] = acc[ii][jj] * 0.125f;
        }
    }
}

// ---------------- K6: fused geo prior + softmax + vl reduction per m ----------
// dyn smem: L[16*1024] | wgs[16*64] | kms[16*64](unused slot kept simple) | hred[16]
__global__ __launch_bounds__(256) void k_attn(const float* __restrict__ wg_w,
                                              const float* __restrict__ wg_b) {
    extern __shared__ float sh[];
    float* L    = sh;                 // 16384
    float* wgs  = sh + 16384;         // 1024
    float* hred = sh + 16384 + 1024;  // 16
    __shared__ float wgb_s[NH];
    int m = blockIdx.x, t = threadIdx.x;
    for (int idx = t; idx < NH * 64; idx += 256) wgs[idx] = wg_w[idx];
    if (t < NH) wgb_s[t] = wg_b[t];
    float cxm = g_sgeo[m*4+0], cym = g_sgeo[m*4+1], wm = g_sgeo[m*4+2], hm = g_sgeo[m*4+3];
    float dmf[8];
    #pragma unroll
    for (int f = 0; f < 8; f++) dmf[f] = expf(-(float)f * 0.86346941f); // 1000^(-f/8)
    __syncthreads();

    // phase A: logits L[h][n]
    for (int n = t; n < NROI; n += 256) {
        float cxn = g_sgeo[n*4+0], cyn = g_sgeo[n*4+1], wn = g_sgeo[n*4+2], hn = g_sgeo[n*4+3];
        float pos[4];
        pos[0] = logf(fmaxf(fabsf((cxm - cxn) / wm), 1e-3f));
        pos[1] = logf(fmaxf(fabsf((cym - cyn) / hm), 1e-3f));
        pos[2] = logf(wm / wn);
        pos[3] = logf(hm / hn);
        float sn[32], cn[32];
        #pragma unroll
        for (int p = 0; p < 4; p++) {
            float base = 100.f * pos[p];
            #pragma unroll
            for (int f = 0; f < 8; f++)
                sincosf(base * dmf[f], &sn[p*8+f], &cn[p*8+f]);
        }
        for (int h = 0; h < NH; h++) {
            float g = wgb_s[h];
            const float* wr = wgs + h * 64;
            #pragma unroll
            for (int gi = 0; gi < 32; gi++)
                g += sn[gi] * wr[gi] + cn[gi] * wr[32 + gi];
            float sc = g_S[(h << 20) + (m << 10) + n];
            // log(max(relu(g),1e-6)) == log(max(g,1e-6))
            L[(h << 10) + n] = logf(fmaxf(g, 1e-6f)) + sc;
        }
    }
    __syncthreads();

    // phase B: per-head softmax + vl-weighted sum (8 warps, 2 heads each)
    int warp = t >> 5, lane = t & 31;
    for (int h = warp; h < NH; h += 8) {
        const float* Lh  = L + (h << 10);
        const float* vlh = g_vl + h * NROI;
        float M = -1e30f;
        for (int n = lane; n < NROI; n += 32) M = fmaxf(M, Lh[n]);
        #pragma unroll
        for (int o = 16; o; o >>= 1) M = fmaxf(M, __shfl_xor_sync(0xffffffffu, M, o));
        float ss = 0.f, ps = 0.f;
        for (int n = lane; n < NROI; n += 32) {
            float e = expf(Lh[n] - M);
            ss += e;
            ps += e * vlh[n];
        }
        #pragma unroll
        for (int o = 16; o; o >>= 1) {
            ss += __shfl_xor_sync(0xffffffffu, ss, o);
            ps += __shfl_xor_sync(0xffffffffu, ps, o);
        }
        if (lane == 0) hred[h] = ps / ss;
    }
    __syncthreads();
    if (t == 0) {
        float a = 0.f;
        for (int h = 0; h < NH; h++) a += hred[h];
        g_attn[m] = a;
    }
}

// ---------------- K7: final output assembly -----------------------------------
__global__ void k_out(const float* __restrict__ logit_b, float* __restrict__ out) {
    int i = blockIdx.x * blockDim.x + threadIdx.x;
    if (i >= NROI) return;
    float x = g_attn[i] + g_sflw[i] + logit_b[0];
    float s1 = 1.0f / (1.0f + expf(-x));
    out[i] = s1 * g_sprob[i];                        // nms_scores
    out[NROI + i] = (float)(g_slabel[i] - 1);        // labels - 1
    #pragma unroll
    for (int j = 0; j < 4; j++)
        out[2 * NROI + i * 4 + j] = g_sbbox[i * 4 + j];
}

// ---------------- launch -------------------------------------------------------
extern "C" void kernel_launch(void* const* d_in, const int* in_sizes, int n_in,
                              void* d_out, int out_size) {
    const float* sample_roi  = (const float*)d_in[0];
    const float* roi_cls_loc = (const float*)d_in[1];
    const float* roi_score   = (const float*)d_in[2];
    const float* app         = (const float*)d_in[3];
    const int*   size        = (const int*)  d_in[4];
    const float* rank_w      = (const float*)d_in[5];
    const float* rank_b      = (const float*)d_in[6];
    const float* feat_w      = (const float*)d_in[7];
    const float* feat_b      = (const float*)d_in[8];
    const float* logit_w     = (const float*)d_in[9];
    const float* logit_b     = (const float*)d_in[10];
    const float* wg_w        = (const float*)d_in[11];
    const float* wg_b        = (const float*)d_in[12];
    const float* wk_w        = (const float*)d_in[13];
    const float* wk_b        = (const float*)d_in[14];
    const float* wq_w        = (const float*)d_in[15];
    const float* wq_b        = (const float*)d_in[16];
    const float* wv_w        = (const float*)d_in[17];
    const float* wv_b        = (const float*)d_in[18];
    float* out = (float*)d_out;

    const int attn_smem = (16 * 1024 + 1024 + 16) * (int)sizeof(float); // 69,760 B
    cudaFuncSetAttribute(k_attn, cudaFuncAttributeMaxDynamicSharedMemorySize, attn_smem);

    k_perroi<<<4, 256>>>(sample_roi, roi_cls_loc, roi_score, size);
    k_rank<<<4, 256>>>();
    k_emb<<<NROI, DF>>>(app, rank_w, rank_b, feat_w, feat_b, logit_w);
    k_wvl<<<8, 256>>>(wv_w, wv_b, logit_w);
    k_kqv<<<NROI, 256>>>(wk_w, wk_b, wq_w, wq_b);
    k_score<<<dim3(16, 16, 16), 256>>>();
    k_attn<<<NROI, 256, attn_smem>>>(wg_w, wg_b);
    k_out<<<4, 256>>>(logit_b, out);
}

// round 7
// speedup vs baseline: 1.8184x; 1.8184x over previous
#include <cuda_runtime.h>
#include <math.h>

#define NROI 1024
#define NCLS 21
#define APP  1024
#define DF   128
#define NH   16
#define DK   64

typedef unsigned long long ull;

// ---------------- f32x2 packed-math helpers (sm_103a) -------------------------
__device__ __forceinline__ ull pk2(float lo, float hi) {
    ull r; asm("mov.b64 %0,{%1,%2};" : "=l"(r) : "f"(lo), "f"(hi)); return r;
}
__device__ __forceinline__ float2 upk(ull v) {
    float2 f; asm("mov.b64 {%0,%1},%2;" : "=f"(f.x), "=f"(f.y) : "l"(v)); return f;
}
__device__ __forceinline__ void fma2(ull &c, ull a, ull b) {
    asm("fma.rn.f32x2 %0,%1,%2,%0;" : "+l"(c) : "l"(a), "l"(b));
}
__device__ __forceinline__ ull mul2(ull a, ull b) {
    ull r; asm("mul.rn.f32x2 %0,%1,%2;" : "=l"(r) : "l"(a), "l"(b)); return r;
}

// ---------------- scratch (device globals; no allocation allowed) -------------
__device__ float g_S[NH * NROI * NROI];   // 64 MB scores [h][m][n]
__device__ float g_K[NH * NROI * DK];
__device__ float g_Q[NH * NROI * DK];
__device__ float g_emb[NROI * DF];
__device__ float g_vl[NH * NROI];
__device__ float g_wvl[NH * DF];
__device__ float g_bvl[NH];
__device__ float g_prob[NROI], g_sprob[NROI], g_attn[NROI], g_sflw[NROI];
__device__ float g_bbox[NROI * 4], g_sbbox[NROI * 4];
__device__ __align__(16) float g_sgeo[NROI * 4];
__device__ int   g_label[NROI], g_slabel[NROI], g_order[NROI];

// ---------------- K1: per-ROI softmax / argmax / bbox decode ------------------
__global__ void k_perroi(const float* __restrict__ roi,
                         const float* __restrict__ cls_loc,
                         const float* __restrict__ score,
                         const int*   __restrict__ size) {
    int i = blockIdx.x * blockDim.x + threadIdx.x;
    if (i >= NROI) return;
    const float* s = score + i * NCLS;
    float mx = -1e30f; int am = 0;
    for (int c = 0; c < NCLS; c++) { float v = s[c]; if (v > mx) { mx = v; am = c; } }
    float sum = 0.f;
    for (int c = 0; c < NCLS; c++) sum += expf(s[c] - mx);
    g_prob[i] = 1.0f / sum;
    g_label[i] = am;
    float y0 = roi[i*4+0], x0 = roi[i*4+1], y1 = roi[i*4+2], x1 = roi[i*4+3];
    float h = y1 - y0, w = x1 - x0;
    float cy = y0 + 0.5f * h, cx = x0 + 0.5f * w;
    const float* l = cls_loc + i * (NCLS*4) + am * 4;
    float dy = l[0]*0.1f, dx = l[1]*0.1f, dh = l[2]*0.2f, dw = l[3]*0.2f;
    float ncy = dy*h + cy, ncx = dx*w + cx;
    float nh = expf(dh)*h, nw = expf(dw)*w;
    float b0 = ncy - 0.5f*nh, b1 = ncx - 0.5f*nw, b2 = ncy + 0.5f*nh, b3 = ncx + 0.5f*nw;
    // clamp quirk of the reference: even class -> all coords clamped to size[0],
    // odd class -> size[1]
    float lim = ((am & 1) == 0) ? (float)size[0] : (float)size[1];
    b0 = fminf(fmaxf(b0, 0.f), lim);
    b1 = fminf(fmaxf(b1, 0.f), lim);
    b2 = fminf(fmaxf(b2, 0.f), lim);
    b3 = fminf(fmaxf(b3, 0.f), lim);
    g_bbox[i*4+0]=b0; g_bbox[i*4+1]=b1; g_bbox[i*4+2]=b2; g_bbox[i*4+3]=b3;
}

// ---------------- K2: stable descending rank + scatter ------------------------
__global__ __launch_bounds__(256) void k_rank() {
    __shared__ float sp[NROI];
    int t = threadIdx.x;
    int i = blockIdx.x * 256 + t;
    for (int j = t; j < NROI; j += 256) sp[j] = g_prob[j];
    __syncthreads();
    float p = sp[i];
    int r = 0;
    for (int j = 0; j < NROI; j++) {
        float pj = sp[j];
        r += (pj > p) || (pj == p && j < i);
    }
    g_order[r]  = i;
    g_sprob[r]  = p;
    g_slabel[r] = g_label[i];
    float b0=g_bbox[i*4+0], b1=g_bbox[i*4+1], b2=g_bbox[i*4+2], b3=g_bbox[i*4+3];
    g_sbbox[r*4+0]=b0; g_sbbox[r*4+1]=b1; g_sbbox[r*4+2]=b2; g_sbbox[r*4+3]=b3;
    float cx = (b0+b2)*0.5f, cy = (b1+b3)*0.5f;
    float w  = (b2-b0)+1.0f, h  = (b3-b1)+1.0f;
    g_sgeo[r*4+0]=cx; g_sgeo[r*4+1]=cy; g_sgeo[r*4+2]=w; g_sgeo[r*4+3]=h;
}

// ---------------- K3: emb = sf@feat_w + RE@rank_w + biases  (BM=8 tile) -------
__global__ __launch_bounds__(DF) void k_emb(const float* __restrict__ app,
                                            const float* __restrict__ rank_w,
                                            const float* __restrict__ rank_b,
                                            const float* __restrict__ feat_w,
                                            const float* __restrict__ feat_b,
                                            const float* __restrict__ lw) {
    __shared__ __align__(16) float arow[8][APP];
    __shared__ __align__(16) float rerow[8][APP];
    __shared__ int   s_oi[8];
    __shared__ float s_red[8][4];
    int i0 = blockIdx.x * 8, t = threadIdx.x;
    if (t < 8) s_oi[t] = g_order[i0 + t];
    __syncthreads();
    // load 8 gathered appearance rows (float4) + partial logit dot
    float pl[8];
    #pragma unroll
    for (int r = 0; r < 8; r++) pl[r] = 0.f;
    const float4* app4 = (const float4*)app;
    const float4* lw4  = (const float4*)lw;
    #pragma unroll
    for (int it = 0; it < 16; it++) {
        int idx = t + it * 128;            // 0..2047
        int r = idx >> 8, j4 = idx & 255;
        float4 a = app4[s_oi[r] * 256 + j4];
        *(float4*)&arow[r][j4 * 4] = a;
        float4 l = lw4[j4];
        pl[r] += a.x*l.x + a.y*l.y + a.z*l.z + a.w*l.w;
    }
    // rank embedding rows (precise path; cheap)
    const float LOGW = 6.90775527898f / 512.0f;
    for (int it = 0; it < 64; it++) {
        int idx = t + it * 128;            // 0..8191
        int r = idx >> 10, j = idx & 1023;
        int f = j & 511;
        float arg = (float)(i0 + r) * expf(-(float)f * LOGW);
        rerow[r][j] = (j < 512) ? sinf(arg) : cosf(arg);
    }
    float bias = feat_b[t] + rank_b[t];
    ull acc[8];
    #pragma unroll
    for (int r = 0; r < 8; r++) acc[r] = pk2(bias, 0.f);
    __syncthreads();
    for (int j4 = 0; j4 < 256; j4++) {
        int jb = j4 * 4;
        float fw0 = feat_w[(jb+0)*DF + t], fw1 = feat_w[(jb+1)*DF + t];
        float fw2 = feat_w[(jb+2)*DF + t], fw3 = feat_w[(jb+3)*DF + t];
        float rw0 = rank_w[(jb+0)*DF + t], rw1 = rank_w[(jb+1)*DF + t];
        float rw2 = rank_w[(jb+2)*DF + t], rw3 = rank_w[(jb+3)*DF + t];
        ull fp01 = pk2(fw0, fw1), fp23 = pk2(fw2, fw3);
        ull rp01 = pk2(rw0, rw1), rp23 = pk2(rw2, rw3);
        #pragma unroll
        for (int r = 0; r < 8; r++) {
            ulonglong2 a2 = *(const ulonglong2*)&arow[r][jb];
            ulonglong2 e2 = *(const ulonglong2*)&rerow[r][jb];
            fma2(acc[r], a2.x, fp01); fma2(acc[r], a2.y, fp23);
            fma2(acc[r], e2.x, rp01); fma2(acc[r], e2.y, rp23);
        }
    }
    #pragma unroll
    for (int r = 0; r < 8; r++) {
        float2 v = upk(acc[r]);
        g_emb[(i0 + r) * DF + t] = v.x + v.y;
    }
    // reduce sflw partials
    int warp = t >> 5, lane = t & 31;
    #pragma unroll
    for (int r = 0; r < 8; r++) {
        float v = pl[r];
        #pragma unroll
        for (int o = 16; o; o >>= 1) v += __shfl_xor_sync(0xffffffffu, v, o);
        if (lane == 0) s_red[r][warp] = v;
    }
    __syncthreads();
    if (t < 8) g_sflw[i0 + t] = s_red[t][0] + s_red[t][1] + s_red[t][2] + s_red[t][3];
}

// ---------------- K4a: wvl[h] = wv_w[h] @ lw_h (coalesced, warp-per-row) ------
__global__ __launch_bounds__(128) void k_wvl(const float* __restrict__ wv_w,
                                             const float* __restrict__ wv_b,
                                             const float* __restrict__ lw) {
    __shared__ float lwh[DK];
    int h = blockIdx.x;
    int t = threadIdx.x, warp = t >> 5, lane = t & 31;
    if (t < DK) lwh[t] = lw[h * DK + t];
    __syncthreads();
    for (int d = warp; d < DF; d += 4) {
        const float* W = wv_w + (h * DF + d) * DK;
        float a = W[lane] * lwh[lane] + W[lane + 32] * lwh[lane + 32];
        #pragma unroll
        for (int o = 16; o; o >>= 1) a += __shfl_xor_sync(0xffffffffu, a, o);
        if (lane == 0) g_wvl[h * DF + d] = a;
    }
    if (warp == 0) {
        const float* B = wv_b + h * DK;
        float a = B[lane] * lwh[lane] + B[lane + 32] * lwh[lane + 32];
        #pragma unroll
        for (int o = 16; o; o >>= 1) a += __shfl_xor_sync(0xffffffffu, a, o);
        if (lane == 0) g_bvl[h] = a;
    }
}

// ---------------- K4b: k/q projections + vl  (BM=8 rows, TN=8 cols) -----------
__global__ __launch_bounds__(256) void k_kqv(const float* __restrict__ wk_w,
                                             const float* __restrict__ wk_b,
                                             const float* __restrict__ wq_w,
                                             const float* __restrict__ wq_b) {
    __shared__ __align__(16) float es[DF][8];   // [d][r]
    int i0 = blockIdx.x * 8, t = threadIdx.x;
    for (int idx = t; idx < 8 * DF; idx += 256) {
        int r = idx >> 7, d = idx & 127;
        es[d][r] = g_emb[(i0 + r) * DF + d];
    }
    __syncthreads();
    const float* wp[8]; float bias[8];
    #pragma unroll
    for (int c = 0; c < 8; c++) {
        int p = t + (c << 8);
        if (p < 1024) { int h = p >> 6, kk = p & 63; wp[c] = wk_w + h * DF * DK + kk; bias[c] = wk_b[p]; }
        else          { int q = p - 1024; int h = q >> 6, kk = q & 63; wp[c] = wq_w + h * DF * DK + kk; bias[c] = wq_b[q]; }
    }
    ull acc[8][4];
    #pragma unroll
    for (int c = 0; c < 8; c++)
        #pragma unroll
        for (int rp = 0; rp < 4; rp++) acc[c][rp] = 0ull;
    for (int d = 0; d < DF; d++) {
        ulonglong2 e0123 = *(const ulonglong2*)&es[d][0];
        ulonglong2 e4567 = *(const ulonglong2*)&es[d][4];
        #pragma unroll
        for (int c = 0; c < 8; c++) {
            float w = wp[c][d << 6];
            ull wd = pk2(w, w);
            fma2(acc[c][0], e0123.x, wd);
            fma2(acc[c][1], e0123.y, wd);
            fma2(acc[c][2], e4567.x, wd);
            fma2(acc[c][3], e4567.y, wd);
        }
    }
    #pragma unroll
    for (int c = 0; c < 8; c++) {
        int p = t + (c << 8);
        float* dst = (p < 1024) ? g_K : g_Q;
        int pp = (p < 1024) ? p : p - 1024;
        int h = pp >> 6, kk = pp & 63;
        #pragma unroll
        for (int rp = 0; rp < 4; rp++) {
            float2 v = upk(acc[c][rp]);
            dst[(h * NROI + i0 + 2*rp    ) * DK + kk] = v.x + bias[c];
            dst[(h * NROI + i0 + 2*rp + 1) * DK + kk] = v.y + bias[c];
        }
    }
    if (t < 128) {
        int h = t >> 3, r = t & 7;
        float a = g_bvl[h];
        for (int d = 0; d < DF; d++) a += es[d][r] * g_wvl[h * DF + d];
        g_vl[(h << 10) + i0 + r] = a;
    }
}

// ---------------- K5: score GEMM, f32x2, transposed smem tiles ----------------
__global__ __launch_bounds__(128) void k_score() {
    __shared__ __align__(16) float Kt[64][68];
    __shared__ __align__(16) float Qt[64][68];
    int h = blockIdx.z, mt = blockIdx.y, nt = blockIdx.x;
    int t = threadIdx.x;
    const float* Kg = g_K + ((h << 10) + mt * 64) * DK;
    const float* Qg = g_Q + ((h << 10) + nt * 64) * DK;
    #pragma unroll
    for (int it = 0; it < 32; it++) {
        int idx = t + it * 128;
        int r = idx >> 6, c = idx & 63;
        Kt[c][r] = Kg[r * DK + c];
        Qt[c][r] = Qg[r * DK + c];
    }
    __syncthreads();
    int ty = t >> 3, tx = t & 7;       // rows ty*4..+3, cols tx*8..+7
    ull acc[4][4];
    #pragma unroll
    for (int i = 0; i < 4; i++)
        #pragma unroll
        for (int j = 0; j < 4; j++) acc[i][j] = 0ull;
    #pragma unroll 8
    for (int kk = 0; kk < 64; kk++) {
        float4 av = *(const float4*)&Kt[kk][ty * 4];
        ulonglong2 b01 = *(const ulonglong2*)&Qt[kk][tx * 8];
        ulonglong2 b23 = *(const ulonglong2*)&Qt[kk][tx * 8 + 4];
        ull a0 = pk2(av.x, av.x), a1 = pk2(av.y, av.y);
        ull a2 = pk2(av.z, av.z), a3 = pk2(av.w, av.w);
        fma2(acc[0][0], a0, b01.x); fma2(acc[0][1], a0, b01.y);
        fma2(acc[0][2], a0, b23.x); fma2(acc[0][3], a0, b23.y);
        fma2(acc[1][0], a1, b01.x); fma2(acc[1][1], a1, b01.y);
        fma2(acc[1][2], a1, b23.x); fma2(acc[1][3], a1, b23.y);
        fma2(acc[2][0], a2, b01.x); fma2(acc[2][1], a2, b01.y);
        fma2(acc[2][2], a2, b23.x); fma2(acc[2][3], a2, b23.y);
        fma2(acc[3][0], a3, b01.x); fma2(acc[3][1], a3, b01.y);
        fma2(acc[3][2], a3, b23.x); fma2(acc[3][3], a3, b23.y);
    }
    ull eighth = pk2(0.125f, 0.125f);
    int base = (h << 20) + ((mt * 64 + ty * 4) << 10) + nt * 64 + tx * 8;
    #pragma unroll
    for (int i = 0; i < 4; i++)
        #pragma unroll
        for (int j = 0; j < 4; j++)
            *(ull*)(g_S + base + (i << 10) + 2 * j) = mul2(acc[i][j], eighth);
}

// ---------------- K6: fused geo prior + product-form softmax + vl reduce ------
// softmax(log(g~) + s) == weights proportional to g~ * exp(s); s bounded small,
// clamp at 60 guards overflow -> exact, no logf needed.
__global__ __launch_bounds__(256) void k_attn(const float* __restrict__ wg_w,
                                              const float* __restrict__ wg_b) {
    extern __shared__ __align__(16) float sh[];
    float* G   = sh;                        // 16*1024 floats
    ull*  wgp  = (ull*)(sh + NH * NROI);    // 16*32 packed weight pairs
    __shared__ float wgb_s[NH];
    __shared__ float hred[NH];
    int m = blockIdx.x, t = threadIdx.x;
    for (int idx = t; idx < NH * 32; idx += 256) {
        int h = idx >> 5, j = idx & 31;
        float lo, hi;
        if (j < 16) { lo = wg_w[h*64 + 2*j];       hi = wg_w[h*64 + 2*j + 1]; }
        else { int jj = j - 16; lo = wg_w[h*64 + 32 + 2*jj]; hi = wg_w[h*64 + 32 + 2*jj + 1]; }
        wgp[idx] = pk2(lo, hi);
    }
    if (t < NH) wgb_s[t] = wg_b[t];
    float4 gm = *(const float4*)&g_sgeo[m * 4];
    __syncthreads();
    const float dmf[8] = {1.0f, 0.42169650342f, 0.17782794100f, 0.07498942093f,
                          0.03162277660f, 0.01333521432f, 0.00562341325f, 0.00237137371f};
    // phase A: geo prior G[h][n]
    for (int n = t; n < NROI; n += 256) {
        float4 gn = *(const float4*)&g_sgeo[n * 4];
        float base4[4];
        base4[0] = 100.f * logf(fmaxf(fabsf((gm.x - gn.x) / gm.z), 1e-3f));
        base4[1] = 100.f * logf(fmaxf(fabsf((gm.y - gn.y) / gm.w), 1e-3f));
        base4[2] = 100.f * logf(gm.z / gn.z);
        base4[3] = 100.f * logf(gm.w / gn.w);
        ull ep[32];
        #pragma unroll
        for (int j2 = 0; j2 < 16; j2++) {
            int gi0 = 2 * j2, gi1 = gi0 + 1;
            float s0, c0, s1, c1;
            __sincosf(base4[gi0 >> 3] * dmf[gi0 & 7], &s0, &c0);
            __sincosf(base4[gi1 >> 3] * dmf[gi1 & 7], &s1, &c1);
            ep[j2]      = pk2(s0, s1);
            ep[16 + j2] = pk2(c0, c1);
        }
        for (int h = 0; h < NH; h++) {
            ull acc = pk2(wgb_s[h], 0.f);
            const ulonglong2* w2 = (const ulonglong2*)(wgp + h * 32);
            #pragma unroll
            for (int j2 = 0; j2 < 16; j2++) {
                ulonglong2 w = w2[j2];
                fma2(acc, ep[2 * j2],     w.x);
                fma2(acc, ep[2 * j2 + 1], w.y);
            }
            float2 f = upk(acc);
            G[(h << 10) + n] = fmaxf(f.x + f.y, 1e-6f);
        }
    }
    __syncthreads();
    // phase B: per-head weighted softmax reduction
    int warp = t >> 5, lane = t & 31;
    for (int h = warp; h < NH; h += 8) {
        const float* Sh = g_S + (h << 20) + (m << 10);
        const float* vh = g_vl + (h << 10);
        const float* Gh = G + (h << 10);
        float ss = 0.f, ps = 0.f;
        for (int n = lane; n < NROI; n += 32) {
            float w = Gh[n] * __expf(fminf(Sh[n], 60.f));
            ss += w; ps += w * vh[n];
        }
        #pragma unroll
        for (int o = 16; o; o >>= 1) {
            ss += __shfl_xor_sync(0xffffffffu, ss, o);
            ps += __shfl_xor_sync(0xffffffffu, ps, o);
        }
        if (lane == 0) hred[h] = ps / ss;
    }
    __syncthreads();
    if (t == 0) {
        float a = 0.f;
        for (int h = 0; h < NH; h++) a += hred[h];
        g_attn[m] = a;
    }
}

// ---------------- K7: final output assembly -----------------------------------
__global__ void k_out(const float* __restrict__ logit_b, float* __restrict__ out) {
    int i = blockIdx.x * blockDim.x + threadIdx.x;
    if (i >= NROI) return;
    float x = g_attn[i] + g_sflw[i] + logit_b[0];
    float s1 = 1.0f / (1.0f + expf(-x));
    out[i] = s1 * g_sprob[i];
    out[NROI + i] = (float)(g_slabel[i] - 1);
    #pragma unroll
    for (int j = 0; j < 4; j++)
        out[2 * NROI + i * 4 + j] = g_sbbox[i * 4 + j];
}

// ---------------- launch -------------------------------------------------------
extern "C" void kernel_launch(void* const* d_in, const int* in_sizes, int n_in,
                              void* d_out, int out_size) {
    const float* sample_roi  = (const float*)d_in[0];
    const float* roi_cls_loc = (const float*)d_in[1];
    const float* roi_score   = (const float*)d_in[2];
    const float* app         = (const float*)d_in[3];
    const int*   size        = (const int*)  d_in[4];
    const float* rank_w      = (const float*)d_in[5];
    const float* rank_b      = (const float*)d_in[6];
    const float* feat_w      = (const float*)d_in[7];
    const float* feat_b      = (const float*)d_in[8];
    const float* logit_w     = (const float*)d_in[9];
    const float* logit_b     = (const float*)d_in[10];
    const float* wg_w        = (const float*)d_in[11];
    const float* wg_b        = (const float*)d_in[12];
    const float* wk_w        = (const float*)d_in[13];
    const float* wk_b        = (const float*)d_in[14];
    const float* wq_w        = (const float*)d_in[15];
    const float* wq_b        = (const float*)d_in[16];
    const float* wv_w        = (const float*)d_in[17];
    const float* wv_b        = (const float*)d_in[18];
    float* out = (float*)d_out;

    const int attn_smem = (NH * NROI) * 4 + (NH * 32) * 8;   // 65536 + 4096
    cudaFuncSetAttribute(k_attn, cudaFuncAttributeMaxDynamicSharedMemorySize, attn_smem);

    k_perroi<<<4, 256>>>(sample_roi, roi_cls_loc, roi_score, size);
    k_rank<<<4, 256>>>();
    k_emb<<<NROI / 8, DF>>>(app, rank_w, rank_b, feat_w, feat_b, logit_w);
    k_wvl<<<NH, 128>>>(wv_w, wv_b, logit_w);
    k_kqv<<<NROI / 8, 256>>>(wk_w, wk_b, wq_w, wq_b);
    k_score<<<dim3(16, 16, 16), 128>>>();
    k_attn<<<NROI, 256, attn_smem>>>(wg_w, wg_b);
    k_out<<<4, 256>>>(logit_b, out);
}

// round 9
// speedup vs baseline: 2.0612x; 1.1335x over previous
#include <cuda_runtime.h>
#include <cuda_bf16.h>
#include <math.h>
#include <stdint.h>

#define NROI 1024
#define NCLS 21
#define APP  1024
#define DF   128
#define NH   16
#define DK   64

typedef unsigned long long ull;
typedef unsigned int u32;

// ---------------- f32x2 packed-math helpers (sm_103a) -------------------------
__device__ __forceinline__ ull pk2(float lo, float hi) {
    ull r; asm("mov.b64 %0,{%1,%2};" : "=l"(r) : "f"(lo), "f"(hi)); return r;
}
__device__ __forceinline__ float2 upk(ull v) {
    float2 f; asm("mov.b64 {%0,%1},%2;" : "=f"(f.x), "=f"(f.y) : "l"(v)); return f;
}
__device__ __forceinline__ void fma2(ull &c, ull a, ull b) {
    asm("fma.rn.f32x2 %0,%1,%2,%0;" : "+l"(c) : "l"(a), "l"(b));
}

// ---------------- HMMA m16n8k16 bf16 (baseline sm_80+ feature) ----------------
__device__ __forceinline__ void mma_bf16(float* c, const u32* a, const u32* b) {
    asm volatile("mma.sync.aligned.m16n8k16.row.col.f32.bf16.bf16.f32 "
        "{%0,%1,%2,%3},{%4,%5,%6,%7},{%8,%9},{%0,%1,%2,%3};"
        : "+f"(c[0]), "+f"(c[1]), "+f"(c[2]), "+f"(c[3])
        : "r"(a[0]), "r"(a[1]), "r"(a[2]), "r"(a[3]), "r"(b[0]), "r"(b[1]));
}

// ---------------- scratch (device globals; no allocation allowed) -------------
__device__ float g_S[NH * NROI * NROI];   // 64 MB scores [h][m][n]
__device__ __align__(16) __nv_bfloat16 g_Kh[NH*NROI*DK], g_Kl[NH*NROI*DK];
__device__ __align__(16) __nv_bfloat16 g_Qh[NH*NROI*DK], g_Ql[NH*NROI*DK];
__device__ float g_emb[NROI * DF];
__device__ float g_vl[NH * NROI];
__device__ float g_wvl[NH * DF];
__device__ float g_bvl[NH];
__device__ float g_prob[NROI], g_sprob[NROI], g_sflw[NROI];
__device__ float g_bbox[NROI * 4], g_sbbox[NROI * 4];
__device__ __align__(16) float4 g_geoA[NROI];   // cx, cy, log w, log h
__device__ __align__(8)  float2 g_geoB[NROI];   // 1/w, 1/h
__device__ int   g_label[NROI], g_slabel[NROI], g_order[NROI];

// ---------------- K1: per-ROI decode (blocks 0-3) + wvl (blocks 4-19) ---------
__global__ __launch_bounds__(256) void k_front(const float* __restrict__ roi,
                                               const float* __restrict__ cls_loc,
                                               const float* __restrict__ score,
                                               const int*   __restrict__ size,
                                               const float* __restrict__ wv_w,
                                               const float* __restrict__ wv_b,
                                               const float* __restrict__ lw) {
    __shared__ float lwh[DK];
    int b = blockIdx.x, t = threadIdx.x;
    if (b < 4) {
        int i = b * 256 + t;
        const float* s = score + i * NCLS;
        float mx = -1e30f; int am = 0;
        for (int c = 0; c < NCLS; c++) { float v = s[c]; if (v > mx) { mx = v; am = c; } }
        float sum = 0.f;
        for (int c = 0; c < NCLS; c++) sum += expf(s[c] - mx);
        g_prob[i] = 1.0f / sum;
        g_label[i] = am;
        float y0 = roi[i*4+0], x0 = roi[i*4+1], y1 = roi[i*4+2], x1 = roi[i*4+3];
        float h = y1 - y0, w = x1 - x0;
        float cy = y0 + 0.5f * h, cx = x0 + 0.5f * w;
        const float* l = cls_loc + i * (NCLS*4) + am * 4;
        float dy = l[0]*0.1f, dx = l[1]*0.1f, dh = l[2]*0.2f, dw = l[3]*0.2f;
        float ncy = dy*h + cy, ncx = dx*w + cx;
        float nh = expf(dh)*h, nw = expf(dw)*w;
        float b0 = ncy - 0.5f*nh, b1 = ncx - 0.5f*nw, b2 = ncy + 0.5f*nh, b3 = ncx + 0.5f*nw;
        // reference clamp quirk: even class -> all coords clamp to size[0], odd -> size[1]
        float lim = ((am & 1) == 0) ? (float)size[0] : (float)size[1];
        b0 = fminf(fmaxf(b0, 0.f), lim); b1 = fminf(fmaxf(b1, 0.f), lim);
        b2 = fminf(fmaxf(b2, 0.f), lim); b3 = fminf(fmaxf(b3, 0.f), lim);
        g_bbox[i*4+0]=b0; g_bbox[i*4+1]=b1; g_bbox[i*4+2]=b2; g_bbox[i*4+3]=b3;
        return;
    }
    int h = b - 4;
    if (t < DK) lwh[t] = lw[h * DK + t];
    __syncthreads();
    int d = t >> 1, half = t & 1;
    const float4* W  = (const float4*)(wv_w + (h * DF + d) * DK + half * 32);
    float a = 0.f;
    #pragma unroll
    for (int q = 0; q < 8; q++) {
        float4 w4 = W[q];
        const float* l4 = lwh + half * 32 + q * 4;
        a += w4.x*l4[0] + w4.y*l4[1] + w4.z*l4[2] + w4.w*l4[3];
    }
    a += __shfl_xor_sync(0xffffffffu, a, 1);
    if (!half) g_wvl[h * DF + d] = a;
    if (t < 32) {
        float pb = wv_b[h*DK + t] * lwh[t] + wv_b[h*DK + t + 32] * lwh[t + 32];
        #pragma unroll
        for (int o = 16; o; o >>= 1) pb += __shfl_xor_sync(0xffffffffu, pb, o);
        if (t == 0) g_bvl[h] = pb;
    }
}

// ---------------- K2: stable descending rank + scatter ------------------------
__global__ __launch_bounds__(256) void k_rank() {
    __shared__ float sp[NROI];
    int t = threadIdx.x;
    int i = blockIdx.x * 256 + t;
    for (int j = t; j < NROI; j += 256) sp[j] = g_prob[j];
    __syncthreads();
    float p = sp[i];
    int r = 0;
    for (int j = 0; j < NROI; j++) {
        float pj = sp[j];
        r += (pj > p) || (pj == p && j < i);
    }
    g_order[r]  = i;
    g_sprob[r]  = p;
    g_slabel[r] = g_label[i];
    float b0=g_bbox[i*4+0], b1=g_bbox[i*4+1], b2=g_bbox[i*4+2], b3=g_bbox[i*4+3];
    g_sbbox[r*4+0]=b0; g_sbbox[r*4+1]=b1; g_sbbox[r*4+2]=b2; g_sbbox[r*4+3]=b3;
    float cx = (b0+b2)*0.5f, cy = (b1+b3)*0.5f;
    float w  = (b2-b0)+1.0f, h  = (b3-b1)+1.0f;
    g_geoA[r] = make_float4(cx, cy, logf(w), logf(h));
    g_geoB[r] = make_float2(1.0f / w, 1.0f / h);
}

// ---------------- K3: emb = sf@feat_w + RE@rank_w + biases  (BM=8 tile) -------
__global__ __launch_bounds__(DF) void k_emb(const float* __restrict__ app,
                                            const float* __restrict__ rank_w,
                                            const float* __restrict__ rank_b,
                                            const float* __restrict__ feat_w,
                                            const float* __restrict__ feat_b,
                                            const float* __restrict__ lw) {
    __shared__ __align__(16) float arow[8][APP];
    __shared__ __align__(16) float rerow[8][APP];
    __shared__ int   s_oi[8];
    __shared__ float s_red[8][4];
    int i0 = blockIdx.x * 8, t = threadIdx.x;
    if (t < 8) s_oi[t] = g_order[i0 + t];
    __syncthreads();
    float pl[8];
    #pragma unroll
    for (int r = 0; r < 8; r++) pl[r] = 0.f;
    const float4* app4 = (const float4*)app;
    const float4* lw4  = (const float4*)lw;
    #pragma unroll
    for (int it = 0; it < 16; it++) {
        int idx = t + it * 128;
        int r = idx >> 8, j4 = idx & 255;
        float4 a = app4[s_oi[r] * 256 + j4];
        *(float4*)&arow[r][j4 * 4] = a;
        float4 l = lw4[j4];
        pl[r] += a.x*l.x + a.y*l.y + a.z*l.z + a.w*l.w;
    }
    // rank embedding: 1 expf + 2 sincosf per frequency, recurrence across rows
    const float LOGW = 6.90775527898f / 512.0f;
    for (int f = t; f < 512; f += 128) {
        float a = expf(-(float)f * LOGW);
        float s0, c0, sa, ca;
        sincosf((float)i0 * a, &s0, &c0);
        sincosf(a, &sa, &ca);
        #pragma unroll
        for (int r = 0; r < 8; r++) {
            rerow[r][f] = s0; rerow[r][f + 512] = c0;
            float s1 = s0*ca + c0*sa, c1 = c0*ca - s0*sa;
            s0 = s1; c0 = c1;
        }
    }
    float bias = feat_b[t] + rank_b[t];
    ull acc[8];
    #pragma unroll
    for (int r = 0; r < 8; r++) acc[r] = pk2(bias, 0.f);
    __syncthreads();
    for (int j4 = 0; j4 < 256; j4++) {
        int jb = j4 * 4;
        ull fp01 = pk2(feat_w[(jb+0)*DF + t], feat_w[(jb+1)*DF + t]);
        ull fp23 = pk2(feat_w[(jb+2)*DF + t], feat_w[(jb+3)*DF + t]);
        ull rp01 = pk2(rank_w[(jb+0)*DF + t], rank_w[(jb+1)*DF + t]);
        ull rp23 = pk2(rank_w[(jb+2)*DF + t], rank_w[(jb+3)*DF + t]);
        #pragma unroll
        for (int r = 0; r < 8; r++) {
            ulonglong2 a2 = *(const ulonglong2*)&arow[r][jb];
            ulonglong2 e2 = *(const ulonglong2*)&rerow[r][jb];
            fma2(acc[r], a2.x, fp01); fma2(acc[r], a2.y, fp23);
            fma2(acc[r], e2.x, rp01); fma2(acc[r], e2.y, rp23);
        }
    }
    #pragma unroll
    for (int r = 0; r < 8; r++) {
        float2 v = upk(acc[r]);
        g_emb[(i0 + r) * DF + t] = v.x + v.y;
    }
    int warp = t >> 5, lane = t & 31;
    #pragma unroll
    for (int r = 0; r < 8; r++) {
        float v = pl[r];
        #pragma unroll
        for (int o = 16; o; o >>= 1) v += __shfl_xor_sync(0xffffffffu, v, o);
        if (lane == 0) s_red[r][warp] = v;
    }
    __syncthreads();
    if (t < 8) g_sflw[i0 + t] = s_red[t][0] + s_red[t][1] + s_red[t][2] + s_red[t][3];
}

// ---------------- K4: k/q projections (bf16 hi/lo out) + vl -------------------
__global__ __launch_bounds__(256) void k_kqv(const float* __restrict__ wk_w,
                                             const float* __restrict__ wk_b,
                                             const float* __restrict__ wq_w,
                                             const float* __restrict__ wq_b) {
    __shared__ __align__(16) float es[DF][8];
    int i0 = blockIdx.x * 8, t = threadIdx.x;
    for (int idx = t; idx < 8 * DF; idx += 256) {
        int r = idx >> 7, d = idx & 127;
        es[d][r] = g_emb[(i0 + r) * DF + d];
    }
    __syncthreads();
    const float* wp[8]; float bias[8];
    #pragma unroll
    for (int c = 0; c < 8; c++) {
        int p = t + (c << 8);
        if (p < 1024) { int h = p >> 6, kk = p & 63; wp[c] = wk_w + h * DF * DK + kk; bias[c] = wk_b[p]; }
        else          { int q = p - 1024; int h = q >> 6, kk = q & 63; wp[c] = wq_w + h * DF * DK + kk; bias[c] = wq_b[q]; }
    }
    ull acc[8][4];
    #pragma unroll
    for (int c = 0; c < 8; c++)
        #pragma unroll
        for (int rp = 0; rp < 4; rp++) acc[c][rp] = 0ull;
    for (int d = 0; d < DF; d++) {
        ulonglong2 e0123 = *(const ulonglong2*)&es[d][0];
        ulonglong2 e4567 = *(const ulonglong2*)&es[d][4];
        #pragma unroll
        for (int c = 0; c < 8; c++) {
            float w = wp[c][d << 6];
            ull wd = pk2(w, w);
            fma2(acc[c][0], e0123.x, wd);
            fma2(acc[c][1], e0123.y, wd);
            fma2(acc[c][2], e4567.x, wd);
            fma2(acc[c][3], e4567.y, wd);
        }
    }
    #pragma unroll
    for (int c = 0; c < 8; c++) {
        int p = t + (c << 8);
        bool isK = (p < 1024);
        int pp = isK ? p : p - 1024;
        int h = pp >> 6, kk = pp & 63;
        #pragma unroll
        for (int rp = 0; rp < 4; rp++) {
            float2 v = upk(acc[c][rp]);
            #pragma unroll
            for (int e = 0; e < 2; e++) {
                float val = ((e == 0) ? v.x : v.y) + bias[c];
                int idx = (h * NROI + i0 + 2*rp + e) * DK + kk;
                __nv_bfloat16 hi = __float2bfloat16(val);
                __nv_bfloat16 lo = __float2bfloat16(val - __bfloat162float(hi));
                if (isK) { g_Kh[idx] = hi; g_Kl[idx] = lo; }
                else     { g_Qh[idx] = hi; g_Ql[idx] = lo; }
            }
        }
    }
    if (t < 128) {
        int h = t >> 3, r = t & 7;
        float a = g_bvl[h];
        for (int d = 0; d < DF; d++) a += es[d][r] * g_wvl[h * DF + d];
        g_vl[(h << 10) + i0 + r] = a;
    }
}

// ---------------- K5: HMMA bf16-split score GEMM ------------------------------
// block tile 128m x 64n; 8 warps, each 32m x 32n (2 m16-tiles x 4 n8-tiles)
// S = Khi.Qhi^T + Khi.Qlo^T + Klo.Qhi^T  (compensated bf16 split, fp32 accum)
#define LDP 33   // padded row stride in u32 (64 bf16 = 32 u32 + 1 pad)
__global__ __launch_bounds__(256) void k_score_mma() {
    extern __shared__ __align__(16) u32 sm[];
    u32* KHs = sm;
    u32* KLs = sm + 128 * LDP;
    u32* QHs = sm + 2 * 128 * LDP;
    u32* QLs = sm + 2 * 128 * LDP + 64 * LDP;
    int t = threadIdx.x;
    int nt = blockIdx.x, mt = blockIdx.y, h = blockIdx.z;
    const u32* gKH = (const u32*)g_Kh + ((h << 10) + mt * 128) * 32;
    const u32* gKL = (const u32*)g_Kl + ((h << 10) + mt * 128) * 32;
    const u32* gQH = (const u32*)g_Qh + ((h << 10) + nt * 64) * 32;
    const u32* gQL = (const u32*)g_Ql + ((h << 10) + nt * 64) * 32;
    #pragma unroll
    for (int it = 0; it < 16; it++) {
        int idx = t + it * 256;            // 0..4095
        int row = idx >> 5, c = idx & 31;
        KHs[row * LDP + c] = gKH[idx];
        KLs[row * LDP + c] = gKL[idx];
    }
    #pragma unroll
    for (int it = 0; it < 8; it++) {
        int idx = t + it * 256;            // 0..2047
        int row = idx >> 5, c = idx & 31;
        QHs[row * LDP + c] = gQH[idx];
        QLs[row * LDP + c] = gQL[idx];
    }
    __syncthreads();
    int wid = t >> 5, lane = t & 31;
    int m0 = (wid >> 1) * 32, n0 = (wid & 1) * 32;
    int r = lane >> 2, cp2 = (lane & 3) * 2;   // k-pair start (bf16 units)
    float acc[2][4][4];
    #pragma unroll
    for (int i = 0; i < 2; i++)
        #pragma unroll
        for (int j = 0; j < 4; j++)
            #pragma unroll
            for (int e = 0; e < 4; e++) acc[i][j][e] = 0.f;
    #pragma unroll
    for (int kc = 0; kc < 4; kc++) {
        int cb = kc * 8 + (cp2 >> 1);          // u32 col index
        u32 ah[2][4], al[2][4];
        #pragma unroll
        for (int i = 0; i < 2; i++) {
            int ra = m0 + i * 16 + r;
            ah[i][0] = KHs[ra * LDP + cb];       al[i][0] = KLs[ra * LDP + cb];
            ah[i][1] = KHs[(ra+8) * LDP + cb];   al[i][1] = KLs[(ra+8) * LDP + cb];
            ah[i][2] = KHs[ra * LDP + cb + 4];   al[i][2] = KLs[ra * LDP + cb + 4];
            ah[i][3] = KHs[(ra+8) * LDP + cb+4]; al[i][3] = KLs[(ra+8) * LDP + cb+4];
        }
        u32 bh[4][2], bl[4][2];
        #pragma unroll
        for (int j = 0; j < 4; j++) {
            int rb = n0 + j * 8 + r;           // n index (only r<8 matters per spec)
            bh[j][0] = QHs[rb * LDP + cb];     bl[j][0] = QLs[rb * LDP + cb];
            bh[j][1] = QHs[rb * LDP + cb + 4]; bl[j][1] = QLs[rb * LDP + cb + 4];
        }
        #pragma unroll
        for (int i = 0; i < 2; i++)
            #pragma unroll
            for (int j = 0; j < 4; j++) {
                mma_bf16(acc[i][j], ah[i], bh[j]);
                mma_bf16(acc[i][j], ah[i], bl[j]);
                mma_bf16(acc[i][j], al[i], bh[j]);
            }
    }
    #pragma unroll
    for (int i = 0; i < 2; i++) {
        int m = mt * 128 + m0 + i * 16 + r;
        #pragma unroll
        for (int j = 0; j < 4; j++) {
            float* dst = g_S + (h << 20) + (m << 10) + nt * 64 + n0 + j * 8 + cp2;
            *(float2*)dst = make_float2(acc[i][j][0] * 0.125f, acc[i][j][1] * 0.125f);
            *(float2*)(dst + (8 << 10)) = make_float2(acc[i][j][2] * 0.125f, acc[i][j][3] * 0.125f);
        }
    }
}

// ---------------- K6: fused geo prior + product softmax + vl + output ---------
__global__ __launch_bounds__(256) void k_attn(const float* __restrict__ wg_w,
                                              const float* __restrict__ wg_b,
                                              const float* __restrict__ logit_b,
                                              float* __restrict__ out) {
    extern __shared__ __align__(16) float sh[];
    float* G  = sh;                       // 16*1024
    ull* wgp  = (ull*)(sh + NH * NROI);   // 16*32 packed pairs
    __shared__ float wgb_s[NH];
    __shared__ float hred[NH];
    int m = blockIdx.x, t = threadIdx.x;
    for (int idx = t; idx < NH * 32; idx += 256) {
        int h = idx >> 5, j = idx & 31;
        float lo, hi;
        if (j < 16) { lo = wg_w[h*64 + 2*j];            hi = wg_w[h*64 + 2*j + 1]; }
        else { int jj = j - 16; lo = wg_w[h*64 + 32 + 2*jj]; hi = wg_w[h*64 + 32 + 2*jj + 1]; }
        wgp[idx] = pk2(lo, hi);
    }
    if (t < NH) wgb_s[t] = wg_b[t];
    float4 gm = g_geoA[m];
    float2 gi = g_geoB[m];
    __syncthreads();
    const float dmf[8] = {1.0f, 0.42169650342f, 0.17782794100f, 0.07498942093f,
                          0.03162277660f, 0.01333521432f, 0.00562341325f, 0.00237137371f};
    for (int n = t; n < NROI; n += 256) {
        float4 gn = g_geoA[n];
        float base4[4];
        base4[0] = 100.f * __logf(fmaxf(fabsf((gm.x - gn.x) * gi.x), 1e-3f));
        base4[1] = 100.f * __logf(fmaxf(fabsf((gm.y - gn.y) * gi.y), 1e-3f));
        base4[2] = 100.f * (gm.z - gn.z);
        base4[3] = 100.f * (gm.w - gn.w);
        ull ep[32];
        #pragma unroll
        for (int j2 = 0; j2 < 16; j2++) {
            int gi0 = 2 * j2, gi1 = gi0 + 1;
            float s0, c0, s1, c1;
            __sincosf(base4[gi0 >> 3] * dmf[gi0 & 7], &s0, &c0);
            __sincosf(base4[gi1 >> 3] * dmf[gi1 & 7], &s1, &c1);
            ep[j2]      = pk2(s0, s1);
            ep[16 + j2] = pk2(c0, c1);
        }
        for (int h = 0; h < NH; h++) {
            ull acc = pk2(wgb_s[h], 0.f);
            const ulonglong2* w2 = (const ulonglong2*)(wgp + h * 32);
            #pragma unroll
            for (int j2 = 0; j2 < 16; j2++) {
                ulonglong2 w = w2[j2];
                fma2(acc, ep[2 * j2],     w.x);
                fma2(acc, ep[2 * j2 + 1], w.y);
            }
            float2 f = upk(acc);
            G[(h << 10) + n] = fmaxf(f.x + f.y, 1e-6f);
        }
    }
    __syncthreads();
    int warp = t >> 5, lane = t & 31;
    for (int h = warp; h < NH; h += 8) {
        const float* Sh = g_S + (h << 20) + (m << 10);
        const float* vh = g_vl + (h << 10);
        const float* Gh = G + (h << 10);
        float ss = 0.f, ps = 0.f;
        for (int n = lane; n < NROI; n += 32) {
            float w = Gh[n] * __expf(fminf(Sh[n], 60.f));
            ss += w; ps += w * vh[n];
        }
        #pragma unroll
        for (int o = 16; o; o >>= 1) {
            ss += __shfl_xor_sync(0xffffffffu, ss, o);
            ps += __shfl_xor_sync(0xffffffffu, ps, o);
        }
        if (lane == 0) hred[h] = ps / ss;
    }
    __syncthreads();
    if (t == 0) {
        float a = 0.f;
        for (int h = 0; h < NH; h++) a += hred[h];
        float x = a + g_sflw[m] + logit_b[0];
        float s1 = 1.0f / (1.0f + expf(-x));
        out[m] = s1 * g_sprob[m];
        out[NROI + m] = (float)(g_slabel[m] - 1);
        #pragma unroll
        for (int j = 0; j < 4; j++)
            out[2 * NROI + m * 4 + j] = g_sbbox[m * 4 + j];
    }
}

// ---------------- launch -------------------------------------------------------
extern "C" void kernel_launch(void* const* d_in, const int* in_sizes, int n_in,
                              void* d_out, int out_size) {
    const float* sample_roi  = (const float*)d_in[0];
    const float* roi_cls_loc = (const float*)d_in[1];
    const float* roi_score   = (const float*)d_in[2];
    const float* app         = (const float*)d_in[3];
    const int*   size        = (const int*)  d_in[4];
    const float* rank_w      = (const float*)d_in[5];
    const float* rank_b      = (const float*)d_in[6];
    const float* feat_w      = (const float*)d_in[7];
    const float* feat_b      = (const float*)d_in[8];
    const float* logit_w     = (const float*)d_in[9];
    const float* logit_b     = (const float*)d_in[10];
    const float* wg_w        = (const float*)d_in[11];
    const float* wg_b        = (const float*)d_in[12];
    const float* wk_w        = (const float*)d_in[13];
    const float* wk_b        = (const float*)d_in[14];
    const float* wq_w        = (const float*)d_in[15];
    const float* wq_b        = (const float*)d_in[16];
    const float* wv_w        = (const float*)d_in[17];
    const float* wv_b        = (const float*)d_in[18];
    float* out = (float*)d_out;

    const int score_smem = (2 * 128 * LDP + 2 * 64 * LDP) * (int)sizeof(u32); // 50688
    const int attn_smem  = (NH * NROI) * 4 + (NH * 32) * 8;                   // 69632
    cudaFuncSetAttribute(k_score_mma, cudaFuncAttributeMaxDynamicSharedMemorySize, score_smem);
    cudaFuncSetAttribute(k_attn, cudaFuncAttributeMaxDynamicSharedMemorySize, attn_smem);

    k_front<<<20, 256>>>(sample_roi, roi_cls_loc, roi_score, size, wv_w, wv_b, logit_w);
    k_rank<<<4, 256>>>();
    k_emb<<<NROI / 8, DF>>>(app, rank_w, rank_b, feat_w, feat_b, logit_w);
    k_kqv<<<NROI / 8, 256>>>(wk_w, wk_b, wq_w, wq_b);
    k_score_mma<<<dim3(16, 8, 16), 256, score_smem>>>();
    k_attn<<<NROI, 256, attn_smem>>>(wg_w, wg_b, logit_b, out);
}